// round 2
// baseline (speedup 1.0000x reference)
#include <cuda_runtime.h>
#include <math.h>

// Problem constants
#define BB     8
#define KK     2048
#define DD     1024
#define NINNER 2048
#define MM     (BB * KK)      // 16384 rows
#define EPSV   1e-5f

// ---------------------------------------------------------------------------
// Scratch (allocation-free: __device__ globals) — 448 MB total
// ---------------------------------------------------------------------------
__device__ float g_h  [(size_t)MM * DD];       //  64 MB  rmsnorm output
__device__ float g_u  [(size_t)MM * NINNER];   // 128 MB  silu(u)
__device__ float g_zs [(size_t)MM * NINNER];   // 128 MB  silu(z)
__device__ float g_lam[(size_t)MM * NINNER];   // 128 MB  lambda, overwritten in-place by s*silu(z)

// ---------------------------------------------------------------------------
// RMSNorm: one block per row (1024 floats), 256 threads, float4
// ---------------------------------------------------------------------------
__global__ __launch_bounds__(256) void rmsnorm_kernel(
    const float* __restrict__ x, const float* __restrict__ w,
    float* __restrict__ h)
{
    const int row = blockIdx.x;
    const int t   = threadIdx.x;
    const float4* xr = reinterpret_cast<const float4*>(x + (size_t)row * DD);
    float4 v = xr[t];
    float ss = v.x * v.x + v.y * v.y + v.z * v.z + v.w * v.w;

    #pragma unroll
    for (int o = 16; o > 0; o >>= 1)
        ss += __shfl_xor_sync(0xFFFFFFFFu, ss, o);

    __shared__ float wsum[8];
    if ((t & 31) == 0) wsum[t >> 5] = ss;
    __syncthreads();

    float sum = 0.f;
    #pragma unroll
    for (int i = 0; i < 8; i++) sum += wsum[i];

    const float scale = rsqrtf(sum * (1.0f / DD) + EPSV);

    const float4 wv = reinterpret_cast<const float4*>(w)[t];
    float4 o;
    o.x = v.x * scale * wv.x;
    o.y = v.y * scale * wv.y;
    o.z = v.z * scale * wv.z;
    o.w = v.w * scale * wv.w;
    reinterpret_cast<float4*>(h + (size_t)row * DD)[t] = o;
}

// ---------------------------------------------------------------------------
// NT GEMM: C[M,N] = A[M,KD] * Bw[N,KD]^T, fp32 FFMA, 128x128x16 tiles,
// 256 threads, 8x8 register micro-tile. All dims are multiples of tile sizes.
//
// MODE 0: c <  NINNER -> out0[r,c]        = silu(v)
//         c >= NINNER -> out1[r,c-NINNER] = silu(v)   (z branch: store silu(z))
// MODE 1: out0[r,c] = sigmoid(v + bias[c])
// MODE 2: out0[r,c] = resid[r,c] + v
// ---------------------------------------------------------------------------
#define BM  128
#define BN  128
#define BKT 16
#define TM  8
#define TN  8

template <int MODE>
__global__ __launch_bounds__(256) void gemm_nt(
    const float* __restrict__ A, const float* __restrict__ Bw,
    int M, int N, int KD,
    const float* __restrict__ bias, const float* __restrict__ resid,
    float* __restrict__ out0, float* __restrict__ out1)
{
    __shared__ float As[BKT][BM];
    __shared__ float Bs[BKT][BN];

    const int bm = blockIdx.y * BM;
    const int bn = blockIdx.x * BN;
    const int tid = threadIdx.x;          // 0..255
    const int tm = (tid >> 4) * TM;       // 0,8,...,120
    const int tn = (tid & 15) * TN;       // 0,8,...,120

    float acc[TM][TN];
    #pragma unroll
    for (int i = 0; i < TM; i++)
        #pragma unroll
        for (int j = 0; j < TN; j++) acc[i][j] = 0.f;

    for (int k0 = 0; k0 < KD; k0 += BKT) {
        #pragma unroll
        for (int i = 0; i < 2; i++) {
            int f = tid + i * 256;
            int r = f >> 2;             // 0..127
            int c = (f & 3) << 2;       // 0,4,8,12
            float4 v = *reinterpret_cast<const float4*>(
                A + (size_t)(bm + r) * KD + k0 + c);
            As[c + 0][r] = v.x; As[c + 1][r] = v.y;
            As[c + 2][r] = v.z; As[c + 3][r] = v.w;
        }
        #pragma unroll
        for (int i = 0; i < 2; i++) {
            int f = tid + i * 256;
            int r = f >> 2;
            int c = (f & 3) << 2;
            float4 v = *reinterpret_cast<const float4*>(
                Bw + (size_t)(bn + r) * KD + k0 + c);
            Bs[c + 0][r] = v.x; Bs[c + 1][r] = v.y;
            Bs[c + 2][r] = v.z; Bs[c + 3][r] = v.w;
        }
        __syncthreads();

        #pragma unroll
        for (int kk = 0; kk < BKT; kk++) {
            float a[TM], b[TN];
            #pragma unroll
            for (int i = 0; i < TM; i++) a[i] = As[kk][tm + i];
            #pragma unroll
            for (int j = 0; j < TN; j++) b[j] = Bs[kk][tn + j];
            #pragma unroll
            for (int i = 0; i < TM; i++)
                #pragma unroll
                for (int j = 0; j < TN; j++)
                    acc[i][j] = fmaf(a[i], b[j], acc[i][j]);
        }
        __syncthreads();
    }

    #pragma unroll
    for (int i = 0; i < TM; i++) {
        const int r = bm + tm + i;
        #pragma unroll
        for (int j = 0; j < TN; j++) {
            const int c = bn + tn + j;
            float v = acc[i][j];
            if (MODE == 0) {
                float sil = v / (1.0f + expf(-v));   // silu(v)
                if (c < NINNER) {
                    out0[(size_t)r * NINNER + c] = sil;            // silu(u)
                } else {
                    out1[(size_t)r * NINNER + (c - NINNER)] = sil; // silu(z)
                }
            } else if (MODE == 1) {
                float t = v + bias[c];
                out0[(size_t)r * N + c] = 1.0f / (1.0f + expf(-t));
            } else {
                out0[(size_t)r * N + c] = resid[(size_t)r * N + c] + v;
            }
        }
    }
}

// ---------------------------------------------------------------------------
// Sequential scan over K per (batch, channel):
//   s_k = u_k + lam_k * (s_{k-1} - u_k)
// fused with output s * silu(z); writes IN-PLACE over lam (each lam element
// is read exactly once before its slot is overwritten).
// ---------------------------------------------------------------------------
__global__ __launch_bounds__(256) void scan_kernel(
    float* __restrict__ lam,            // in: lambda, out: s*silu(z)
    const float* __restrict__ u,        // silu(u)
    const float* __restrict__ zs)       // silu(z)
{
    const int idx = blockIdx.x * blockDim.x + threadIdx.x;  // 0..16383
    const int b = idx >> 11;            // / NINNER
    const int j = idx & (NINNER - 1);
    size_t off = ((size_t)b * KK) * NINNER + j;
    float s = 0.f;
    #pragma unroll 4
    for (int k = 0; k < KK; k++) {
        const float l  = lam[off];
        const float uu = __ldg(u + off);
        const float zz = __ldg(zs + off);
        s = fmaf(l, s - uu, uu);
        lam[off] = s * zz;
        off += NINNER;
    }
}

// ---------------------------------------------------------------------------
// Launch
// ---------------------------------------------------------------------------
extern "C" void kernel_launch(void* const* d_in, const int* in_sizes, int n_in,
                              void* d_out, int out_size)
{
    const float* x      = (const float*)d_in[0];
    const float* w_norm = (const float*)d_in[1];
    const float* W_in   = (const float*)d_in[2];   // [2*NINNER, DD]
    const float* W_dt   = (const float*)d_in[3];   // [NINNER, NINNER]
    const float* b_dt   = (const float*)d_in[4];   // [NINNER]
    const float* W_out  = (const float*)d_in[5];   // [DD, NINNER]
    float* out = (float*)d_out;

    float *h, *u, *zs, *lam;
    cudaGetSymbolAddress((void**)&h,   g_h);
    cudaGetSymbolAddress((void**)&u,   g_u);
    cudaGetSymbolAddress((void**)&zs,  g_zs);
    cudaGetSymbolAddress((void**)&lam, g_lam);

    // 1. RMSNorm
    rmsnorm_kernel<<<MM, 256>>>(x, w_norm, h);

    // 2. uv = h @ W_in^T ; split, silu(u), silu(z)  (M=16384, N=4096, KD=1024)
    {
        dim3 grid((2 * NINNER) / BN, MM / BM);
        gemm_nt<0><<<grid, 256>>>(h, W_in, MM, 2 * NINNER, DD,
                                  nullptr, nullptr, u, zs);
    }

    // 3. lam = sigmoid(u @ W_dt^T + b_dt)  (M=16384, N=2048, KD=2048)
    {
        dim3 grid(NINNER / BN, MM / BM);
        gemm_nt<1><<<grid, 256>>>(u, W_dt, MM, NINNER, NINNER,
                                  b_dt, nullptr, lam, nullptr);
    }

    // 4. scan; lam buffer becomes s*silu(z) in-place
    scan_kernel<<<MM / 256, 256>>>(lam, u, zs);

    // 5. y = (s*silu(z)) @ W_out^T + x  (M=16384, N=1024, KD=2048)
    {
        dim3 grid(DD / BN, MM / BM);
        gemm_nt<2><<<grid, 256>>>(lam, W_out, MM, DD, NINNER,
                                  nullptr, x, out, nullptr);
    }
}

// round 6
// speedup vs baseline: 2.0226x; 2.0226x over previous
#include <cuda_runtime.h>
#include <cuda_bf16.h>
#include <math.h>
#include <stdint.h>

// Problem constants
#define BB     8
#define KK     2048
#define DD     1024
#define NINNER 2048
#define MM     (BB * KK)      // 16384 rows
#define EPSV   1e-5f

// GEMM tiling
#define BM 128
#define BN 128
#define BK 32
#define PAD 8
#define LDSS (BK + PAD)       // 40 bf16 row stride in SMEM

// ---------------------------------------------------------------------------
// Scratch (allocation-free: __device__ globals) — 448 MB total
// ---------------------------------------------------------------------------
__device__ float g_h  [(size_t)MM * DD];       //  64 MB  rmsnorm output
__device__ float g_u  [(size_t)MM * NINNER];   // 128 MB  silu(u)
__device__ float g_zs [(size_t)MM * NINNER];   // 128 MB  silu(z)
__device__ float g_lam[(size_t)MM * NINNER];   // 128 MB  lambda -> s*silu(z) in place

// ---------------------------------------------------------------------------
// Helpers
// ---------------------------------------------------------------------------
__device__ __forceinline__ uint32_t smem_u32(const void* p) {
    uint32_t a;
    asm("{ .reg .u64 t; cvta.to.shared.u64 t, %1; cvt.u32.u64 %0, t; }"
        : "=r"(a) : "l"(p));
    return a;
}

__device__ __forceinline__ void ldsm_x4(uint32_t* r, uint32_t addr) {
    asm volatile("ldmatrix.sync.aligned.m8n8.x4.shared.b16 {%0,%1,%2,%3}, [%4];"
        : "=r"(r[0]), "=r"(r[1]), "=r"(r[2]), "=r"(r[3]) : "r"(addr));
}

__device__ __forceinline__ void mma_bf16(float* c, const uint32_t* a, const uint32_t* b) {
    asm volatile(
        "mma.sync.aligned.m16n8k16.row.col.f32.bf16.bf16.f32 "
        "{%0,%1,%2,%3}, {%4,%5,%6,%7}, {%8,%9}, {%0,%1,%2,%3};"
        : "+f"(c[0]), "+f"(c[1]), "+f"(c[2]), "+f"(c[3])
        : "r"(a[0]), "r"(a[1]), "r"(a[2]), "r"(a[3]), "r"(b[0]), "r"(b[1]));
}

__device__ __forceinline__ uint32_t packbf2(float lo, float hi) {
    __nv_bfloat162 t = __floats2bfloat162_rn(lo, hi);
    return reinterpret_cast<uint32_t&>(t);
}

// Split a float4 into bf16 hi + bf16 lo residual, store 8B each to smem
__device__ __forceinline__ void split_store(
    float4 v, __nv_bfloat16* hi, __nv_bfloat16* lo, int o)
{
    uint32_t h01 = packbf2(v.x, v.y);
    uint32_t h23 = packbf2(v.z, v.w);
    __nv_bfloat162 bh01 = reinterpret_cast<__nv_bfloat162&>(h01);
    __nv_bfloat162 bh23 = reinterpret_cast<__nv_bfloat162&>(h23);
    uint32_t l01 = packbf2(v.x - __low2float(bh01), v.y - __high2float(bh01));
    uint32_t l23 = packbf2(v.z - __low2float(bh23), v.w - __high2float(bh23));
    *reinterpret_cast<uint2*>(hi + o) = make_uint2(h01, h23);
    *reinterpret_cast<uint2*>(lo + o) = make_uint2(l01, l23);
}

// ---------------------------------------------------------------------------
// RMSNorm: one block per row (1024 floats), 256 threads, float4
// ---------------------------------------------------------------------------
__global__ __launch_bounds__(256) void rmsnorm_kernel(
    const float* __restrict__ x, const float* __restrict__ w,
    float* __restrict__ h)
{
    const int row = blockIdx.x;
    const int t   = threadIdx.x;
    float4 v = reinterpret_cast<const float4*>(x + (size_t)row * DD)[t];
    float ss = v.x * v.x + v.y * v.y + v.z * v.z + v.w * v.w;

    #pragma unroll
    for (int o = 16; o > 0; o >>= 1)
        ss += __shfl_xor_sync(0xFFFFFFFFu, ss, o);

    __shared__ float wsum[8];
    if ((t & 31) == 0) wsum[t >> 5] = ss;
    __syncthreads();

    float sum = 0.f;
    #pragma unroll
    for (int i = 0; i < 8; i++) sum += wsum[i];

    const float scale = rsqrtf(sum * (1.0f / DD) + EPSV);
    const float4 wv = reinterpret_cast<const float4*>(w)[t];
    float4 o;
    o.x = v.x * scale * wv.x;
    o.y = v.y * scale * wv.y;
    o.z = v.z * scale * wv.z;
    o.w = v.w * scale * wv.w;
    reinterpret_cast<float4*>(h + (size_t)row * DD)[t] = o;
}

// ---------------------------------------------------------------------------
// mma.sync bf16x3 NT GEMM: C[M,N] = A[M,KD] * Bw[N,KD]^T (fp32 in, ~fp32 out)
//
// 128x128x32 CTA tile, 8 warps (2m x 4n), warp tile 64x32 as 4x4 m16n8k16.
// Per K=16 step: 3 MMAs (hi*hi, hi*lo, lo*hi) per logical tile, fp32 accum.
// Software pipeline: STS(kt); sync; LDG(kt+1); compute(kt); sync.
//
// MODE 0: c <  NINNER -> out0[r,c]        = silu(v)
//         c >= NINNER -> out1[r,c-NINNER] = silu(v)
// MODE 1: out0[r,c] = sigmoid(v + bias[c])      (row stride NINNER)
// MODE 2: out0[r,c] = resid[r,c] + v            (row stride DD)
// ---------------------------------------------------------------------------
template <int MODE>
__global__ __launch_bounds__(256, 1) void gemm_mma(
    const float* __restrict__ A, const float* __restrict__ Bw, int KD,
    const float* __restrict__ bias, const float* __restrict__ resid,
    float* __restrict__ out0, float* __restrict__ out1)
{
    __shared__ __align__(16) __nv_bfloat16 sA_hi[BM * LDSS];
    __shared__ __align__(16) __nv_bfloat16 sA_lo[BM * LDSS];
    __shared__ __align__(16) __nv_bfloat16 sB_hi[BN * LDSS];
    __shared__ __align__(16) __nv_bfloat16 sB_lo[BN * LDSS];

    const int tid  = threadIdx.x;
    const int lane = tid & 31;
    const int wid  = tid >> 5;
    const int warp_m = wid >> 2;   // 0..1  (64 rows each)
    const int warp_n = wid & 3;    // 0..3  (32 cols each)
    const int bm = blockIdx.y * BM;
    const int bn = blockIdx.x * BN;
    const int NT = KD / BK;

    // Staging: thread -> (row, 16-col half)
    const int srow  = tid >> 1;
    const int shalf = (tid & 1) * 16;
    const float* aptr = A  + (size_t)(bm + srow) * KD + shalf;
    const float* bptr = Bw + (size_t)(bn + srow) * KD + shalf;
    const int sto = srow * LDSS + shalf;

    // ldmatrix per-lane addressing
    const uint32_t a_hi_b = smem_u32(sA_hi);
    const uint32_t a_lo_b = smem_u32(sA_lo);
    const uint32_t b_hi_b = smem_u32(sB_hi);
    const uint32_t b_lo_b = smem_u32(sB_lo);
    const int a_row0 = warp_m * 64 + (lane & 15);
    const int a_kadd = (lane >> 4) * 8;
    const int b_row0 = warp_n * 32 + ((lane >> 4) & 1) * 8 + (lane & 7);
    const int b_kadd = ((lane >> 3) & 1) * 8;

    float acc[4][4][4];
    #pragma unroll
    for (int i = 0; i < 4; i++)
        #pragma unroll
        for (int j = 0; j < 4; j++)
            #pragma unroll
            for (int q = 0; q < 4; q++) acc[i][j][q] = 0.f;

    // Preload tile 0
    float4 rA[4], rB[4];
    #pragma unroll
    for (int i = 0; i < 4; i++) {
        rA[i] = *reinterpret_cast<const float4*>(aptr + i * 4);
        rB[i] = *reinterpret_cast<const float4*>(bptr + i * 4);
    }

    for (int kt = 0; kt < NT; kt++) {
        // Stage current tile to SMEM (bf16 hi/lo split)
        #pragma unroll
        for (int i = 0; i < 4; i++) {
            split_store(rA[i], sA_hi, sA_lo, sto + i * 4);
            split_store(rB[i], sB_hi, sB_lo, sto + i * 4);
        }
        __syncthreads();

        // Prefetch next tile from GMEM (latency hidden behind MMAs)
        if (kt + 1 < NT) {
            const int k0 = (kt + 1) * BK;
            #pragma unroll
            for (int i = 0; i < 4; i++) {
                rA[i] = *reinterpret_cast<const float4*>(aptr + k0 + i * 4);
                rB[i] = *reinterpret_cast<const float4*>(bptr + k0 + i * 4);
            }
        }

        // Compute: 2 K=16 steps
        #pragma unroll
        for (int ks = 0; ks < 2; ks++) {
            uint32_t bh[4][2], bl[4][2];
            #pragma unroll
            for (int pair = 0; pair < 2; pair++) {
                const uint32_t off =
                    2u * ((b_row0 + pair * 16) * LDSS + ks * 16 + b_kadd);
                uint32_t r[4];
                ldsm_x4(r, b_hi_b + off);
                bh[pair * 2][0] = r[0]; bh[pair * 2][1] = r[1];
                bh[pair * 2 + 1][0] = r[2]; bh[pair * 2 + 1][1] = r[3];
                ldsm_x4(r, b_lo_b + off);
                bl[pair * 2][0] = r[0]; bl[pair * 2][1] = r[1];
                bl[pair * 2 + 1][0] = r[2]; bl[pair * 2 + 1][1] = r[3];
            }
            #pragma unroll
            for (int mt = 0; mt < 4; mt++) {
                const uint32_t off =
                    2u * ((a_row0 + mt * 16) * LDSS + ks * 16 + a_kadd);
                uint32_t ah[4], al[4];
                ldsm_x4(ah, a_hi_b + off);
                ldsm_x4(al, a_lo_b + off);
                #pragma unroll
                for (int nt = 0; nt < 4; nt++) {
                    mma_bf16(acc[mt][nt], ah, bh[nt]);
                    mma_bf16(acc[mt][nt], ah, bl[nt]);
                    mma_bf16(acc[mt][nt], al, bh[nt]);
                }
            }
        }
        __syncthreads();
    }

    // Epilogue straight from accumulators.
    // acc[mt][nt]: c0,c1 -> (row = l/4, col = 2*(l%4)+0,1), c2,c3 -> row+8
    const int er = bm + warp_m * 64 + (lane >> 2);
    const int ec = bn + warp_n * 32 + (lane & 3) * 2;

    #pragma unroll
    for (int mt = 0; mt < 4; mt++) {
        #pragma unroll
        for (int nt = 0; nt < 4; nt++) {
            #pragma unroll
            for (int half = 0; half < 2; half++) {
                const int r = er + mt * 16 + half * 8;
                const int c = ec + nt * 8;
                float v0 = acc[mt][nt][half * 2 + 0];
                float v1 = acc[mt][nt][half * 2 + 1];
                float2 o;
                if (MODE == 0) {
                    o.x = v0 / (1.0f + expf(-v0));
                    o.y = v1 / (1.0f + expf(-v1));
                    if (bn < NINNER)
                        *reinterpret_cast<float2*>(out0 + (size_t)r * NINNER + c) = o;
                    else
                        *reinterpret_cast<float2*>(out1 + (size_t)r * NINNER + (c - NINNER)) = o;
                } else if (MODE == 1) {
                    float2 bv = *reinterpret_cast<const float2*>(bias + c);
                    o.x = 1.0f / (1.0f + expf(-(v0 + bv.x)));
                    o.y = 1.0f / (1.0f + expf(-(v1 + bv.y)));
                    *reinterpret_cast<float2*>(out0 + (size_t)r * NINNER + c) = o;
                } else {
                    float2 rv = *reinterpret_cast<const float2*>(resid + (size_t)r * DD + c);
                    o.x = rv.x + v0;
                    o.y = rv.y + v1;
                    *reinterpret_cast<float2*>(out0 + (size_t)r * DD + c) = o;
                }
            }
        }
    }
}

// ---------------------------------------------------------------------------
// Sequential scan over K per (batch, channel):  s_k = u_k + lam_k*(s_{k-1}-u_k)
// fused with s * silu(z); writes IN-PLACE over lam.
// ---------------------------------------------------------------------------
__global__ __launch_bounds__(256) void scan_kernel(
    float* __restrict__ lam, const float* __restrict__ u,
    const float* __restrict__ zs)
{
    const int idx = blockIdx.x * blockDim.x + threadIdx.x;  // 0..16383
    const int b = idx >> 11;
    const int j = idx & (NINNER - 1);
    size_t off = ((size_t)b * KK) * NINNER + j;
    float s = 0.f;
    #pragma unroll 4
    for (int k = 0; k < KK; k++) {
        const float l  = lam[off];
        const float uu = __ldg(u + off);
        const float zz = __ldg(zs + off);
        s = fmaf(l, s - uu, uu);
        lam[off] = s * zz;
        off += NINNER;
    }
}

// ---------------------------------------------------------------------------
// Launch
// ---------------------------------------------------------------------------
extern "C" void kernel_launch(void* const* d_in, const int* in_sizes, int n_in,
                              void* d_out, int out_size)
{
    const float* x      = (const float*)d_in[0];
    const float* w_norm = (const float*)d_in[1];
    const float* W_in   = (const float*)d_in[2];   // [2*NINNER, DD]
    const float* W_dt   = (const float*)d_in[3];   // [NINNER, NINNER]
    const float* b_dt   = (const float*)d_in[4];   // [NINNER]
    const float* W_out  = (const float*)d_in[5];   // [DD, NINNER]
    float* out = (float*)d_out;

    float *h, *u, *zs, *lam;
    cudaGetSymbolAddress((void**)&h,   g_h);
    cudaGetSymbolAddress((void**)&u,   g_u);
    cudaGetSymbolAddress((void**)&zs,  g_zs);
    cudaGetSymbolAddress((void**)&lam, g_lam);

    // 1. RMSNorm
    rmsnorm_kernel<<<MM, 256>>>(x, w_norm, h);

    // 2. uv = h @ W_in^T ; split + silu(u) / silu(z)   (M=16384, N=4096, KD=1024)
    {
        dim3 grid((2 * NINNER) / BN, MM / BM);
        gemm_mma<0><<<grid, 256>>>(h, W_in, DD, nullptr, nullptr, u, zs);
    }

    // 3. lam = sigmoid(u @ W_dt^T + b_dt)   (M=16384, N=2048, KD=2048)
    {
        dim3 grid(NINNER / BN, MM / BM);
        gemm_mma<1><<<grid, 256>>>(u, W_dt, NINNER, b_dt, nullptr, lam, nullptr);
    }

    // 4. scan; lam buffer becomes s*silu(z) in place
    scan_kernel<<<MM / 256, 256>>>(lam, u, zs);

    // 5. y = (s*silu(z)) @ W_out^T + x   (M=16384, N=1024, KD=2048)
    {
        dim3 grid(DD / BN, MM / BM);
        gemm_mma<2><<<grid, 256>>>(lam, W_out, NINNER, nullptr, x, out, nullptr);
    }
}